// round 10
// baseline (speedup 1.0000x reference)
#include <cuda_runtime.h>
#include <cuda_bf16.h>

// Fixed shapes per reference: B=4096 users, P=200 slots, tau=1.0
#define NB 4096
#define PMAX 200
#define PCOLS 224          // padded col slots (7 chunks of 32)
#define NTHREADS 256
#define PADV 1.0e15f       // col pad: q=1e30 finite; pad terms -> 1 + (-q)rcp(q) ~ 0

// Scratch (no device allocation allowed -> __device__ globals)
__device__ float g_block_loss[NB];
__device__ unsigned int g_done_count = 0;

__device__ __forceinline__ float fast_rcp(float x) {
    float r;
    asm("rcp.approx.f32 %0, %1;" : "=f"(r) : "f"(x));
    return r;
}

// 2-pair identity: e/(e+n0)+e/(e+n1) = 1 + (e^2 - q) * rcp(e^2 + e*m + q)
//   m=n0+n1, q=n0*n1. Per chunk per row: FADD + FFMA + FFMA(-q mod) + RCP + FFMA.
// The '+1' baselines are added analytically as 2*nIters*NC per thread.
// Pads: col PADV=1e15 -> term ~ 1 - q*rcp(q) (~0, NaN-free even with e=0 rows);
//       row e=0 -> g=-q, d=q -> term ~ 0. Mixed pad reduces EXACTLY to the
//       single real sigmoid (algebraic cancellation of PADV).
template<int NC>
__device__ __forceinline__ float pair_sum(const float2* __restrict__ pos2,
                                          const float2* __restrict__ neg2,
                                          int nIters, int tx, int ty)
{
    float m[NC], q[NC];
    #pragma unroll
    for (int c = 0; c < NC; c++) {
        float2 n = neg2[c * 16 + tx];
        m[c] = n.x + n.y;
        q[c] = n.x * n.y;
    }
    float acc0 = 0.0f, acc1 = 0.0f;
    #pragma unroll 2
    for (int r = 0; r < nIters; r++) {
        float2 e01 = pos2[r * 16 + ty];      // rows 32r+2ty, 32r+2ty+1
        const float e0 = e01.x, e1 = e01.y;
        #pragma unroll
        for (int c = 0; c < NC; c++) {
            float u0 = e0 + m[c];
            float u1 = e1 + m[c];
            float d0 = fmaf(e0, u0, q[c]);
            float d1 = fmaf(e1, u1, q[c]);
            float g0 = fmaf(e0, e0, -q[c]);
            float g1 = fmaf(e1, e1, -q[c]);
            acc0 = fmaf(g0, fast_rcp(d0), acc0);
            acc1 = fmaf(g1, fast_rcp(d1), acc1);
        }
    }
    // analytic baseline: one '+1' per evaluated (row, chunk) term
    return acc0 + acc1 + (float)(2 * nIters * NC);
}

// (256, 4): cap occupancy at 4 blocks/SM -> 64-register budget per thread.
// At the previous implicit 32-reg cap, the NC>=4 paths spill/serialize
// (m[],q[] alone need up to 14 regs), tripling issued instructions.
__global__ __launch_bounds__(NTHREADS, 4) void sauc_kernel(
    const float* __restrict__ scores_pos,
    const float* __restrict__ scores_neg,
    const int* __restrict__ pos_counts,
    float* __restrict__ out)
{
    const int b = blockIdx.x;
    const int tid = threadIdx.x;
    const int tx = tid & 15;
    const int ty = tid >> 4;
    const int p = pos_counts[b];

    __shared__ __align__(8) float s_epos[PCOLS];   // rows: exp(pos), 0-padded
    __shared__ __align__(8) float s_eneg[PCOLS];   // cols: exp(neg), PADV-padded
    __shared__ float s_warp[NTHREADS / 32];
    __shared__ unsigned int s_is_last;

    // Precompute exponentials once per element (tau=1):
    // sigmoid(pos_i - neg_j) = E_i/(E_i+N_j), E=exp(pos), N=exp(neg)
    if (tid < p) {
        s_epos[tid] = __expf(scores_pos[b * PMAX + tid]);
        s_eneg[tid] = __expf(scores_neg[b * PMAX + tid]);
    } else if (tid < PCOLS) {
        s_epos[tid] = 0.0f;
        s_eneg[tid] = PADV;
    }
    __syncthreads();

    const float2* pos2 = (const float2*)s_epos;
    const float2* neg2 = (const float2*)s_eneg;
    const int nc = (p + 31) >> 5;              // col chunks, uniform: 1..7
    const int pe = (p + 1) & ~1;               // rows padded to even only
    const int dr = pe - 2 * ty;
    const int nIters = (dr > 0) ? ((dr + 31) >> 5) : 0;  // per-warp uniform

    float acc;
    switch (nc) {
        case 1:  acc = pair_sum<1>(pos2, neg2, nIters, tx, ty); break;
        case 2:  acc = pair_sum<2>(pos2, neg2, nIters, tx, ty); break;
        case 3:  acc = pair_sum<3>(pos2, neg2, nIters, tx, ty); break;
        case 4:  acc = pair_sum<4>(pos2, neg2, nIters, tx, ty); break;
        case 5:  acc = pair_sum<5>(pos2, neg2, nIters, tx, ty); break;
        case 6:  acc = pair_sum<6>(pos2, neg2, nIters, tx, ty); break;
        default: acc = pair_sum<7>(pos2, neg2, nIters, tx, ty); break;
    }

    // Block reduction
    #pragma unroll
    for (int off = 16; off > 0; off >>= 1)
        acc += __shfl_down_sync(0xffffffffu, acc, off);
    if ((tid & 31) == 0) s_warp[tid >> 5] = acc;
    __syncthreads();
    if (tid == 0) {
        float v = 0.0f;
        #pragma unroll
        for (int w = 0; w < NTHREADS / 32; w++) v += s_warp[w];
        float pf = (float)p;
        g_block_loss[b] = 1.0f - v / (pf * pf);
        __threadfence();
        s_is_last = (atomicAdd(&g_done_count, 1u) == (unsigned)(NB - 1));
    }
    __syncthreads();

    // Last block performs the deterministic fixed-tree mean over 4096 losses.
    if (s_is_last) {
        __threadfence();
        __shared__ float s_red[NTHREADS];
        float a = 0.0f;
        #pragma unroll
        for (int i = tid; i < NB; i += NTHREADS)
            a += g_block_loss[i];
        s_red[tid] = a;
        __syncthreads();
        #pragma unroll
        for (int stride = NTHREADS / 2; stride >= 32; stride >>= 1) {
            if (tid < stride) s_red[tid] += s_red[tid + stride];
            __syncthreads();
        }
        if (tid < 32) {
            float v = s_red[tid];
            #pragma unroll
            for (int off = 16; off > 0; off >>= 1)
                v += __shfl_down_sync(0xffffffffu, v, off);
            if (tid == 0) {
                out[0] = v * (1.0f / (float)NB);
                g_done_count = 0;  // reset for next graph replay
            }
        }
    }
}

extern "C" void kernel_launch(void* const* d_in, const int* in_sizes, int n_in,
                              void* d_out, int out_size)
{
    const float* scores_pos = (const float*)d_in[0];
    const float* scores_neg = (const float*)d_in[1];
    const int*   pos_counts = (const int*)d_in[2];
    float* out = (float*)d_out;

    sauc_kernel<<<NB, NTHREADS>>>(scores_pos, scores_neg, pos_counts, out);
}

// round 11
// speedup vs baseline: 1.0932x; 1.0932x over previous
#include <cuda_runtime.h>
#include <cuda_bf16.h>

// Fixed shapes per reference: B=4096 users, P=200 slots, tau=1.0
#define NB 4096
#define PMAX 200
#define PROWS 224          // row slots (exp(pos)), zero-padded
#define PCOLS 256          // col slots (exp(neg)), PADV-padded to 4 chunks of 64
#define NTHREADS 256
#define PADV 1.0e15f       // col pad: q=1e30 finite; pad term -> 1 - q*rcp(q) ~ 0

// Scratch (no device allocation allowed -> __device__ globals)
__device__ float g_block_loss[NB];
__device__ unsigned int g_done_count = 0;

__device__ __forceinline__ float fast_rcp(float x) {
    float r;
    asm("rcp.approx.f32 %0, %1;" : "=f"(r) : "f"(x));
    return r;
}

// 2-pair identity: e/(e+n0)+e/(e+n1) = 1 + (e^2 - q) * rcp(e^2 + e*m + q)
//   m=n0+n1, q=n0*n1. '+1' baselines added analytically (2*nIters*NC64).
// Pads (validated r9, rel_err 0.0): col PADV -> term ~ 0; row e=0 -> term ~ 0;
// mixed pad reduces to the single real sigmoid.
// Tiling: lane tx (0..31) owns col pairs (64c+2tx, 64c+2tx+1), c<NC64<=4
//   -> m[],q[] need at most 8 registers (vs 14 in the 16-lane layout).
// Warp wy (0..7) processes row pair k=8r+wy via one broadcast LDS.64.
template<int NC64>
__device__ __forceinline__ float pair_sum(const float2* __restrict__ pos2,
                                          const float2* __restrict__ neg2,
                                          int nIters, int tx, int wy)
{
    float m[NC64], q[NC64];
    #pragma unroll
    for (int c = 0; c < NC64; c++) {
        float2 n = neg2[c * 32 + tx];
        m[c] = n.x + n.y;
        q[c] = n.x * n.y;
    }
    float acc0 = 0.0f, acc1 = 0.0f;
    #pragma unroll 1
    for (int r = 0; r < nIters; r++) {
        float2 e01 = pos2[r * 8 + wy];       // rows 2k, 2k+1 (k = 8r+wy)
        const float e0 = e01.x, e1 = e01.y;
        #pragma unroll
        for (int c = 0; c < NC64; c++) {
            float u0 = e0 + m[c];
            float u1 = e1 + m[c];
            float d0 = fmaf(e0, u0, q[c]);
            float d1 = fmaf(e1, u1, q[c]);
            float g0 = fmaf(e0, e0, -q[c]);
            float g1 = fmaf(e1, e1, -q[c]);
            acc0 = fmaf(g0, fast_rcp(d0), acc0);
            acc1 = fmaf(g1, fast_rcp(d1), acc1);
        }
    }
    return acc0 + acc1 + (float)(2 * nIters * NC64);
}

// (256, 6): 42-register budget with 6 blocks/SM residency — enough regs for
// the NC64=4 path (no spills) while keeping ~1536 threads/SM for issue.
__global__ __launch_bounds__(NTHREADS, 6) void sauc_kernel(
    const float* __restrict__ scores_pos,
    const float* __restrict__ scores_neg,
    const int* __restrict__ pos_counts,
    float* __restrict__ out)
{
    const int b = blockIdx.x;
    const int tid = threadIdx.x;
    const int tx = tid & 31;
    const int wy = tid >> 5;
    const int p = pos_counts[b];

    __shared__ __align__(8) float s_epos[PROWS];   // rows: exp(pos), 0-padded
    __shared__ __align__(8) float s_eneg[PCOLS];   // cols: exp(neg), PADV-padded
    __shared__ float s_warp[NTHREADS / 32];
    __shared__ unsigned int s_is_last;

    // Precompute exponentials once per element (tau=1):
    // sigmoid(pos_i - neg_j) = E_i/(E_i+N_j), E=exp(pos), N=exp(neg)
    if (tid < p) {
        s_epos[tid] = __expf(scores_pos[b * PMAX + tid]);
        s_eneg[tid] = __expf(scores_neg[b * PMAX + tid]);
    } else {
        if (tid < PROWS) s_epos[tid] = 0.0f;
        s_eneg[tid] = PADV;
    }
    __syncthreads();

    const float2* pos2 = (const float2*)s_epos;
    const float2* neg2 = (const float2*)s_eneg;
    const int nc64 = (p + 63) >> 6;            // col chunks of 64: 1..4, block-uniform
    const int kpairs = (p + 1) >> 1;           // row pairs
    const int dk = kpairs - wy;
    const int nIters = (dk > 0) ? ((dk + 7) >> 3) : 0;   // warp-uniform

    float acc;
    switch (nc64) {
        case 1:  acc = pair_sum<1>(pos2, neg2, nIters, tx, wy); break;
        case 2:  acc = pair_sum<2>(pos2, neg2, nIters, tx, wy); break;
        case 3:  acc = pair_sum<3>(pos2, neg2, nIters, tx, wy); break;
        default: acc = pair_sum<4>(pos2, neg2, nIters, tx, wy); break;
    }

    // Block reduction
    #pragma unroll
    for (int off = 16; off > 0; off >>= 1)
        acc += __shfl_down_sync(0xffffffffu, acc, off);
    if ((tid & 31) == 0) s_warp[tid >> 5] = acc;
    __syncthreads();
    if (tid == 0) {
        float v = 0.0f;
        #pragma unroll
        for (int w = 0; w < NTHREADS / 32; w++) v += s_warp[w];
        float pf = (float)p;
        g_block_loss[b] = 1.0f - v / (pf * pf);
        __threadfence();
        s_is_last = (atomicAdd(&g_done_count, 1u) == (unsigned)(NB - 1));
    }
    __syncthreads();

    // Last block performs the deterministic fixed-tree mean over 4096 losses.
    if (s_is_last) {
        __threadfence();
        __shared__ float s_red[NTHREADS];
        float a = 0.0f;
        #pragma unroll
        for (int i = tid; i < NB; i += NTHREADS)
            a += g_block_loss[i];
        s_red[tid] = a;
        __syncthreads();
        #pragma unroll
        for (int stride = NTHREADS / 2; stride >= 32; stride >>= 1) {
            if (tid < stride) s_red[tid] += s_red[tid + stride];
            __syncthreads();
        }
        if (tid < 32) {
            float v = s_red[tid];
            #pragma unroll
            for (int off = 16; off > 0; off >>= 1)
                v += __shfl_down_sync(0xffffffffu, v, off);
            if (tid == 0) {
                out[0] = v * (1.0f / (float)NB);
                g_done_count = 0;  // reset for next graph replay
            }
        }
    }
}

extern "C" void kernel_launch(void* const* d_in, const int* in_sizes, int n_in,
                              void* d_out, int out_size)
{
    const float* scores_pos = (const float*)d_in[0];
    const float* scores_neg = (const float*)d_in[1];
    const int*   pos_counts = (const int*)d_in[2];
    float* out = (float*)d_out;

    sauc_kernel<<<NB, NTHREADS>>>(scores_pos, scores_neg, pos_counts, out);
}

// round 12
// speedup vs baseline: 1.1553x; 1.0568x over previous
#include <cuda_runtime.h>
#include <cuda_bf16.h>

// Fixed shapes per reference: B=4096 users, P=200 slots, tau=1.0
#define NB 4096
#define PMAX 200
#define PROWS 224          // row slots (pos/2), padded with -1e30
#define NTHREADS 256
#define ROWPAD -1.0e30f    // tanh(-huge) = -1 exactly -> pair term 0 after +0.5
#define COLPAD  1.0e30f

// Scratch (no device allocation allowed -> __device__ globals)
__device__ float g_block_loss[NB];
__device__ unsigned int g_done_count = 0;

__device__ __forceinline__ float fast_tanh(float x) {
    float r;
    asm("tanh.approx.f32 %0, %1;" : "=f"(r) : "f"(x));
    return r;
}

// sigmoid(p - n) = 0.5*tanh((p-n)/2) + 0.5.  With ph=p/2, nh=n/2:
//   term = 0.5*tanh(ph - nh) + 0.5
// The +0.5 baselines are added analytically (nIters*NC per thread, exact in
// fp32); padded rows/cols contribute 0.5*(-1)+0.5 = 0 exactly (HW tanh
// saturates to -1.0). Per pair: FADD + MUFU.TANH + FFMA(0.5 imm) — 3 instr,
// one register per owned column, nothing else live.
template<int NC>
__device__ __forceinline__ float pair_sum(const float2* __restrict__ ph2,
                                          const float* __restrict__ neg_g,
                                          int p, int nIters, int tx, int wy)
{
    float nh[NC];
    #pragma unroll
    for (int c = 0; c < NC; c++) {
        int j = c * 32 + tx;
        nh[c] = (j < p) ? (0.5f * neg_g[j]) : COLPAD;
    }
    float acc0 = 0.0f, acc1 = 0.0f;
    for (int r = 0; r < nIters; r++) {
        float2 e01 = ph2[r * 8 + wy];        // rows 2k, 2k+1 (k = 8r+wy)
        const float e0 = e01.x, e1 = e01.y;
        #pragma unroll
        for (int c = 0; c < NC; c++) {
            float t0 = fast_tanh(e0 - nh[c]);
            float t1 = fast_tanh(e1 - nh[c]);
            acc0 = fmaf(0.5f, t0, acc0);
            acc1 = fmaf(0.5f, t1, acc1);
        }
    }
    // analytic +0.5 per evaluated pair: 2 rows * NC cols * nIters, halved
    return acc0 + acc1 + (float)(nIters * NC);
}

__global__ __launch_bounds__(NTHREADS) void sauc_kernel(
    const float* __restrict__ scores_pos,
    const float* __restrict__ scores_neg,
    const int* __restrict__ pos_counts,
    float* __restrict__ out)
{
    const int b = blockIdx.x;
    const int tid = threadIdx.x;
    const int tx = tid & 31;
    const int wy = tid >> 5;
    const int p = pos_counts[b];

    __shared__ __align__(8) float s_ph[PROWS];   // pos/2, ROWPAD beyond p
    __shared__ float s_warp[NTHREADS / 32];
    __shared__ unsigned int s_is_last;

    if (tid < PROWS) {
        s_ph[tid] = (tid < p) ? (0.5f * scores_pos[b * PMAX + tid]) : ROWPAD;
    }
    __syncthreads();

    const float2* ph2 = (const float2*)s_ph;
    const float* neg_g = scores_neg + b * PMAX;
    const int nc = (p + 31) >> 5;              // col chunks of 32: 1..7, uniform
    const int kpairs = (p + 1) >> 1;           // row pairs (rows padded to even)
    const int dk = kpairs - wy;
    const int nIters = (dk > 0) ? ((dk + 7) >> 3) : 0;   // warp-uniform

    float acc;
    switch (nc) {
        case 1:  acc = pair_sum<1>(ph2, neg_g, p, nIters, tx, wy); break;
        case 2:  acc = pair_sum<2>(ph2, neg_g, p, nIters, tx, wy); break;
        case 3:  acc = pair_sum<3>(ph2, neg_g, p, nIters, tx, wy); break;
        case 4:  acc = pair_sum<4>(ph2, neg_g, p, nIters, tx, wy); break;
        case 5:  acc = pair_sum<5>(ph2, neg_g, p, nIters, tx, wy); break;
        case 6:  acc = pair_sum<6>(ph2, neg_g, p, nIters, tx, wy); break;
        default: acc = pair_sum<7>(ph2, neg_g, p, nIters, tx, wy); break;
    }

    // Block reduction
    #pragma unroll
    for (int off = 16; off > 0; off >>= 1)
        acc += __shfl_down_sync(0xffffffffu, acc, off);
    if ((tid & 31) == 0) s_warp[tid >> 5] = acc;
    __syncthreads();
    if (tid == 0) {
        float v = 0.0f;
        #pragma unroll
        for (int w = 0; w < NTHREADS / 32; w++) v += s_warp[w];
        float pf = (float)p;
        g_block_loss[b] = 1.0f - v / (pf * pf);
        __threadfence();
        s_is_last = (atomicAdd(&g_done_count, 1u) == (unsigned)(NB - 1));
    }
    __syncthreads();

    // Last block performs the deterministic fixed-tree mean over 4096 losses.
    if (s_is_last) {
        __threadfence();
        __shared__ float s_red[NTHREADS];
        float a = 0.0f;
        #pragma unroll
        for (int i = tid; i < NB; i += NTHREADS)
            a += g_block_loss[i];
        s_red[tid] = a;
        __syncthreads();
        #pragma unroll
        for (int stride = NTHREADS / 2; stride >= 32; stride >>= 1) {
            if (tid < stride) s_red[tid] += s_red[tid + stride];
            __syncthreads();
        }
        if (tid < 32) {
            float v = s_red[tid];
            #pragma unroll
            for (int off = 16; off > 0; off >>= 1)
                v += __shfl_down_sync(0xffffffffu, v, off);
            if (tid == 0) {
                out[0] = v * (1.0f / (float)NB);
                g_done_count = 0;  // reset for next graph replay
            }
        }
    }
}

extern "C" void kernel_launch(void* const* d_in, const int* in_sizes, int n_in,
                              void* d_out, int out_size)
{
    const float* scores_pos = (const float*)d_in[0];
    const float* scores_neg = (const float*)d_in[1];
    const int*   pos_counts = (const int*)d_in[2];
    float* out = (float*)d_out;

    sauc_kernel<<<NB, NTHREADS>>>(scores_pos, scores_neg, pos_counts, out);
}